// round 4
// baseline (speedup 1.0000x reference)
#include <cuda_runtime.h>
#include <cstdint>
#include <cstddef>

#define K27     27
#define N_DOWN  40000
#define N_UP    160000
#define C_DOWN  128
#define C_SKIP  64
#define C_CAT   192
#define C_OUT   96

// Scratch globals (no cudaMalloc allowed)
__device__ float g_up [(size_t)N_UP * C_DOWN];            // 81.92 MB
__device__ float g_WdT[(size_t)K27 * C_DOWN * C_DOWN];    // W_deconv[k]^T [k][n][c], tf32-RN
__device__ float g_WcT[(size_t)K27 * C_OUT  * C_CAT];     // W_conv[k]^T   [k][n][c], tf32-RN

// ---------------------------------------------------------------------------
// Helpers
// ---------------------------------------------------------------------------
__device__ __forceinline__ float to_tf32(float x) {
    float r;
    asm("cvt.rn.tf32.f32 %0, %1;" : "=f"(r) : "f"(x));
    return r;
}
__device__ __forceinline__ void red_add_v4(float* p, float4 v) {
    asm volatile("red.global.add.v4.f32 [%0], {%1, %2, %3, %4};"
                 :: "l"(p), "f"(v.x), "f"(v.y), "f"(v.z), "f"(v.w) : "memory");
}
__device__ __forceinline__ void mma_tf32(float* c, const uint32_t* a,
                                         uint32_t b0, uint32_t b1) {
    asm("mma.sync.aligned.m16n8k8.row.col.f32.tf32.tf32.f32 "
        "{%0,%1,%2,%3}, {%4,%5,%6,%7}, {%8,%9}, {%0,%1,%2,%3};"
        : "+f"(c[0]), "+f"(c[1]), "+f"(c[2]), "+f"(c[3])
        : "r"(a[0]), "r"(a[1]), "r"(a[2]), "r"(a[3]), "r"(b0), "r"(b1));
}
__device__ __forceinline__ uint32_t ldg_u32(const float* p) {
    return __float_as_uint(__ldg(p));
}

// ---------------------------------------------------------------------------
// Zero g_up and d_out
// ---------------------------------------------------------------------------
#define UP_F4   ((N_UP * C_DOWN) / 4)
#define OUT_F4  ((N_UP * C_OUT) / 4)
#define ZERO_F4 (UP_F4 + OUT_F4)

__global__ void __launch_bounds__(256) zero_kernel(float4* __restrict__ out4) {
    int i = blockIdx.x * 256 + threadIdx.x;
    float4 z = make_float4(0.f, 0.f, 0.f, 0.f);
    if (i < UP_F4) reinterpret_cast<float4*>(g_up)[i] = z;
    else           out4[i - UP_F4] = z;
}

// ---------------------------------------------------------------------------
// Weight transpose + tf32 RN rounding
// ---------------------------------------------------------------------------
#define WD_ELEMS (K27 * C_DOWN * C_DOWN)
#define WC_ELEMS (K27 * C_OUT * C_CAT)
__global__ void __launch_bounds__(256) transpose_w_kernel(
    const float* __restrict__ Wd, const float* __restrict__ Wc)
{
    int i = blockIdx.x * 256 + threadIdx.x;
    if (i < WD_ELEMS) {
        int k = i / (C_DOWN * C_DOWN), r = i % (C_DOWN * C_DOWN);
        int n = r / C_DOWN, c = r % C_DOWN;
        g_WdT[i] = to_tf32(Wd[((size_t)k * C_DOWN + c) * C_DOWN + n]);
    } else {
        int j = i - WD_ELEMS;
        int k = j / (C_OUT * C_CAT), r = j % (C_OUT * C_CAT);
        int n = r / C_CAT, c = r % C_CAT;
        g_WcT[j] = to_tf32(Wc[((size_t)k * C_CAT + c) * C_OUT + n]);
    }
}

// ---------------------------------------------------------------------------
// Deconv MMA: tile of 128 edges: D[128,128] = A[128,128] @ WdT[k]^T, scatter.
// A in SMEM (stride 132, %32==4 -> conflict-free frags); B via LDG (L1-hot).
// D staged in SMEM (reuse A region, stride 132). 8 warps: 4M x 2N.
// grid = (313, 27), 256 threads, 2 CTAs/SM.
// ---------------------------------------------------------------------------
#define D_KP   132
#define D_OIDX_F (128 * D_KP)                         // after A
#define D_SMEM   ((128 * D_KP) * 4 + 512)

__global__ void __launch_bounds__(256, 2)
deconv_mma_kernel(const float* __restrict__ down,
                  const int* __restrict__ iin, const int* __restrict__ iout)
{
    extern __shared__ __align__(16) float sm[];
    float* As   = sm;
    int*   oidx = (int*)(sm + D_OIDX_F);

    const int tid = threadIdx.x, wid = tid >> 5, lane = tid & 31;
    const int g = lane >> 2, t4 = lane & 3;
    const int k = blockIdx.y;
    const int ebase = blockIdx.x * 128;
    const int nvalid = min(128, N_DOWN - ebase);

    const int* pin  = iin  + (size_t)k * N_DOWN + ebase;
    const int* pout = iout + (size_t)k * N_DOWN + ebase;
    if (tid < 128) oidx[tid] = (tid < nvalid) ? pout[tid] : -1;

    // Gather A: 2 threads/edge, 16 f4 each
    {
        int e  = tid >> 1;
        int cb = (tid & 1) * 16;
        if (e < nvalid) {
            const float4* src = (const float4*)(down + (size_t)pin[e] * C_DOWN);
#pragma unroll
            for (int j = 0; j < 16; j++) {
                float4 v = src[cb + j];
                v.x = to_tf32(v.x); v.y = to_tf32(v.y);
                v.z = to_tf32(v.z); v.w = to_tf32(v.w);
                *(float4*)&As[e * D_KP + (cb + j) * 4] = v;
            }
        } else {
            float4 z = make_float4(0.f, 0.f, 0.f, 0.f);
#pragma unroll
            for (int j = 0; j < 16; j++)
                *(float4*)&As[e * D_KP + (cb + j) * 4] = z;
        }
    }
    __syncthreads();

    const int mbase = (wid & 3) * 32;
    const int nbase = (wid >> 2) * 64;
    const uint32_t* Ap = (const uint32_t*)As + (mbase + g) * D_KP + t4;
    // B fragment base: row (nbase+g), col t4 in WdT[k] (row stride C_DOWN)
    const float* Bg = g_WdT + (size_t)k * C_DOWN * C_DOWN + (nbase + g) * C_DOWN + t4;

    float c[2][8][4] = {};
#pragma unroll 4
    for (int s = 0; s < 16; s++) {
        const int kk = s * 8;
        uint32_t a[2][4];
#pragma unroll
        for (int mt = 0; mt < 2; mt++) {
            const uint32_t* p = Ap + mt * 16 * D_KP + kk;
            a[mt][0] = p[0]; a[mt][1] = p[8 * D_KP];
            a[mt][2] = p[4]; a[mt][3] = p[8 * D_KP + 4];
        }
#pragma unroll
        for (int j = 0; j < 8; j++) {
            const float* q = Bg + j * 8 * C_DOWN + kk;
            uint32_t b0 = ldg_u32(q), b1 = ldg_u32(q + 4);
            mma_tf32(c[0][j], a[0], b0, b1);
            mma_tf32(c[1][j], a[1], b0, b1);
        }
    }
    __syncthreads();

    // Stage D into SMEM (reuse A region), stride 132
#pragma unroll
    for (int mt = 0; mt < 2; mt++) {
        int row = mbase + mt * 16 + g;
#pragma unroll
        for (int j = 0; j < 8; j++) {
            int col = nbase + j * 8 + 2 * t4;
            *(float2*)&sm[row * D_KP + col]       = make_float2(c[mt][j][0], c[mt][j][1]);
            *(float2*)&sm[(row + 8) * D_KP + col] = make_float2(c[mt][j][2], c[mt][j][3]);
        }
    }
    __syncthreads();

    // Scatter: 4096 f4, 16/thread
#pragma unroll
    for (int t = 0; t < 16; t++) {
        int f = tid + t * 256;
        int e = f >> 5, q = f & 31;
        int o = oidx[e];
        if (o >= 0) {
            float4 v = *(float4*)&sm[e * D_KP + q * 4];
            red_add_v4(g_up + (size_t)o * C_DOWN + q * 4, v);
        }
    }
}

// ---------------------------------------------------------------------------
// Conv MMA: tile of 128 edges: D[128,96] = relu_cat[128,192] @ WcT[k]^T.
// A in SMEM (stride 196); B via LDG; D staged at stride 100 (%32==4).
// 8 warps: 4M x 2N (N=48). grid = (1250, 27), 256 threads, 2 CTAs/SM.
// ---------------------------------------------------------------------------
#define C_KP   196
#define C_DP   100
#define C_OIDX_F (128 * C_KP)
#define C_SMEM   ((128 * C_KP) * 4 + 512)

__global__ void __launch_bounds__(256, 2)
conv_mma_kernel(const float* __restrict__ skip,
                const int* __restrict__ iin, const int* __restrict__ iout,
                float* __restrict__ out)
{
    extern __shared__ __align__(16) float sm[];
    float* As   = sm;
    int*   oidx = (int*)(sm + C_OIDX_F);

    const int tid = threadIdx.x, wid = tid >> 5, lane = tid & 31;
    const int g = lane >> 2, t4 = lane & 3;
    const int k = blockIdx.y;
    const int ebase = blockIdx.x * 128;

    const int* pin  = iin  + (size_t)k * N_UP + ebase;
    const int* pout = iout + (size_t)k * N_UP + ebase;
    if (tid < 128) oidx[tid] = pout[tid];

    // Gather A (fused relu+concat): 2 threads/edge, 24 f4 each.
    {
        int e  = tid >> 1;
        int hh = tid & 1;
        int src = pin[e];
        const float4* up4 = (const float4*)(g_up + (size_t)src * C_DOWN);
        const float4* sk4 = (const float4*)(skip + (size_t)src * C_SKIP);
#pragma unroll
        for (int j = 0; j < 24; j++) {
            int comp = hh * 24 + j;
            float4 v;
            if (comp < 32) {
                v = up4[comp];
                v.x = to_tf32(fmaxf(v.x, 0.f)); v.y = to_tf32(fmaxf(v.y, 0.f));
                v.z = to_tf32(fmaxf(v.z, 0.f)); v.w = to_tf32(fmaxf(v.w, 0.f));
            } else {
                v = sk4[comp - 32];
                v.x = to_tf32(v.x); v.y = to_tf32(v.y);
                v.z = to_tf32(v.z); v.w = to_tf32(v.w);
            }
            *(float4*)&As[e * C_KP + comp * 4] = v;
        }
    }
    __syncthreads();

    const int mbase = (wid & 3) * 32;
    const int nbase = (wid >> 2) * 48;
    const uint32_t* Ap = (const uint32_t*)As + (mbase + g) * C_KP + t4;
    const float* Bg = g_WcT + (size_t)k * C_OUT * C_CAT + (nbase + g) * C_CAT + t4;

    float c[2][6][4] = {};
#pragma unroll 4
    for (int s = 0; s < 24; s++) {
        const int kk = s * 8;
        uint32_t a[2][4];
#pragma unroll
        for (int mt = 0; mt < 2; mt++) {
            const uint32_t* p = Ap + mt * 16 * C_KP + kk;
            a[mt][0] = p[0]; a[mt][1] = p[8 * C_KP];
            a[mt][2] = p[4]; a[mt][3] = p[8 * C_KP + 4];
        }
#pragma unroll
        for (int j = 0; j < 6; j++) {
            const float* q = Bg + j * 8 * C_CAT + kk;
            uint32_t b0 = ldg_u32(q), b1 = ldg_u32(q + 4);
            mma_tf32(c[0][j], a[0], b0, b1);
            mma_tf32(c[1][j], a[1], b0, b1);
        }
    }
    __syncthreads();

    // Stage D into SMEM (reuse A region), stride 100
#pragma unroll
    for (int mt = 0; mt < 2; mt++) {
        int row = mbase + mt * 16 + g;
#pragma unroll
        for (int j = 0; j < 6; j++) {
            int col = nbase + j * 8 + 2 * t4;
            *(float2*)&sm[row * C_DP + col]       = make_float2(c[mt][j][0], c[mt][j][1]);
            *(float2*)&sm[(row + 8) * C_DP + col] = make_float2(c[mt][j][2], c[mt][j][3]);
        }
    }
    __syncthreads();

    // Scatter: 3072 f4, 12/thread
#pragma unroll
    for (int t = 0; t < 12; t++) {
        int f = tid + t * 256;
        int e = f / 24, q = f % 24;
        float4 v = *(float4*)&sm[e * C_DP + q * 4];
        red_add_v4(out + (size_t)oidx[e] * C_OUT + q * 4, v);
    }
}

// ---------------------------------------------------------------------------
// Final ReLU
// ---------------------------------------------------------------------------
__global__ void __launch_bounds__(256) relu_kernel(float4* __restrict__ out4) {
    int i = blockIdx.x * 256 + threadIdx.x;
    float4 v = out4[i];
    v.x = fmaxf(v.x, 0.f); v.y = fmaxf(v.y, 0.f);
    v.z = fmaxf(v.z, 0.f); v.w = fmaxf(v.w, 0.f);
    out4[i] = v;
}

// ---------------------------------------------------------------------------
// Launch
// ---------------------------------------------------------------------------
extern "C" void kernel_launch(void* const* d_in, const int* in_sizes, int n_in,
                              void* d_out, int out_size)
{
    const float* skip = nullptr; const float* down = nullptr;
    const float* Wd = nullptr;   const float* Wc = nullptr;
    const int *d_iin = nullptr, *d_iout = nullptr, *c_iin = nullptr, *c_iout = nullptr;

    for (int i = 0; i < n_in; i++) {
        int sz = in_sizes[i];
        if      (sz == N_UP * C_SKIP)         skip = (const float*)d_in[i];
        else if (sz == N_DOWN * C_DOWN)       down = (const float*)d_in[i];
        else if (sz == K27 * C_DOWN * C_DOWN) Wd   = (const float*)d_in[i];
        else if (sz == K27 * C_CAT * C_OUT)   Wc   = (const float*)d_in[i];
        else if (sz == K27 * N_DOWN) { if (!d_iin) d_iin = (const int*)d_in[i]; else d_iout = (const int*)d_in[i]; }
        else if (sz == K27 * N_UP)   { if (!c_iin) c_iin = (const int*)d_in[i]; else c_iout = (const int*)d_in[i]; }
    }
    float* out = (float*)d_out;

    cudaFuncSetAttribute(deconv_mma_kernel, cudaFuncAttributeMaxDynamicSharedMemorySize, D_SMEM);
    cudaFuncSetAttribute(conv_mma_kernel,   cudaFuncAttributeMaxDynamicSharedMemorySize, C_SMEM);

    zero_kernel<<<ZERO_F4 / 256, 256>>>((float4*)out);
    transpose_w_kernel<<<(WD_ELEMS + WC_ELEMS) / 256, 256>>>(Wd, Wc);
    deconv_mma_kernel<<<dim3((N_DOWN + 127) / 128, K27), 256, D_SMEM>>>(down, d_iin, d_iout);
    conv_mma_kernel<<<dim3(N_UP / 128, K27), 256, C_SMEM>>>(skip, c_iin, c_iout, out);
    relu_kernel<<<OUT_F4 / 256, 256>>>((float4*)out);
}

// round 5
// speedup vs baseline: 2.0010x; 2.0010x over previous
#include <cuda_runtime.h>
#include <cstdint>
#include <cstddef>

#define K27     27
#define N_DOWN  40000
#define N_UP    160000
#define C_DOWN  128
#define C_SKIP  64
#define C_CAT   192
#define C_OUT   96

// Scratch globals (no cudaMalloc allowed)
__device__ float g_up [(size_t)N_UP * C_DOWN];            // 81.92 MB
__device__ float g_WdT[(size_t)K27 * C_DOWN * C_DOWN];    // W_deconv[k]^T [k][n][c], tf32-RN
__device__ float g_WcT[(size_t)K27 * C_OUT  * C_CAT];     // W_conv[k]^T   [k][n][c], tf32-RN

// ---------------------------------------------------------------------------
// Helpers
// ---------------------------------------------------------------------------
__device__ __forceinline__ float to_tf32(float x) {
    float r;
    asm("cvt.rn.tf32.f32 %0, %1;" : "=f"(r) : "f"(x));
    return r;
}
__device__ __forceinline__ void red_add_v4(float* p, float4 v) {
    asm volatile("red.global.add.v4.f32 [%0], {%1, %2, %3, %4};"
                 :: "l"(p), "f"(v.x), "f"(v.y), "f"(v.z), "f"(v.w) : "memory");
}
__device__ __forceinline__ void mma_tf32(float* c, const uint32_t* a,
                                         uint32_t b0, uint32_t b1) {
    asm("mma.sync.aligned.m16n8k8.row.col.f32.tf32.tf32.f32 "
        "{%0,%1,%2,%3}, {%4,%5,%6,%7}, {%8,%9}, {%0,%1,%2,%3};"
        : "+f"(c[0]), "+f"(c[1]), "+f"(c[2]), "+f"(c[3])
        : "r"(a[0]), "r"(a[1]), "r"(a[2]), "r"(a[3]), "r"(b0), "r"(b1));
}

// ---------------------------------------------------------------------------
// Zero g_up and d_out
// ---------------------------------------------------------------------------
#define UP_F4   ((N_UP * C_DOWN) / 4)
#define OUT_F4  ((N_UP * C_OUT) / 4)
#define ZERO_F4 (UP_F4 + OUT_F4)

__global__ void __launch_bounds__(256) zero_kernel(float4* __restrict__ out4) {
    int i = blockIdx.x * 256 + threadIdx.x;
    float4 z = make_float4(0.f, 0.f, 0.f, 0.f);
    if (i < UP_F4) reinterpret_cast<float4*>(g_up)[i] = z;
    else           out4[i - UP_F4] = z;
}

// ---------------------------------------------------------------------------
// Weight transpose + tf32 RN rounding
// ---------------------------------------------------------------------------
#define WD_ELEMS (K27 * C_DOWN * C_DOWN)
#define WC_ELEMS (K27 * C_OUT * C_CAT)
__global__ void __launch_bounds__(256) transpose_w_kernel(
    const float* __restrict__ Wd, const float* __restrict__ Wc)
{
    int i = blockIdx.x * 256 + threadIdx.x;
    if (i < WD_ELEMS) {
        int k = i / (C_DOWN * C_DOWN), r = i % (C_DOWN * C_DOWN);
        int n = r / C_DOWN, c = r % C_DOWN;
        g_WdT[i] = to_tf32(Wd[((size_t)k * C_DOWN + c) * C_DOWN + n]);
    } else {
        int j = i - WD_ELEMS;
        int k = j / (C_OUT * C_CAT), r = j % (C_OUT * C_CAT);
        int n = r / C_CAT, c = r % C_CAT;
        g_WcT[j] = to_tf32(Wc[((size_t)k * C_CAT + c) * C_OUT + n]);
    }
}

// ---------------------------------------------------------------------------
// Deconv MMA: D[128,128] = A[128,128] @ WdT[k]^T, K split into 2 phases of 64.
// A half [128x68], B half [128x68] in SMEM (68 % 32 == 4 -> conflict-free).
// D staged at stride 132 over the A+B region. 8 warps 4M x 2N.
// grid = (313, 27), 256 threads, 2 CTAs/SM (70.7 KB/CTA).
// ---------------------------------------------------------------------------
#define D_HP   68
#define D_DP   132
#define D_B_F  (128 * D_HP)            // 8704
#define D_IDX_F (2 * 128 * D_HP)       // 17408
#define D_SMEM  (D_IDX_F * 4 + 1024)

__global__ void __launch_bounds__(256, 2)
deconv_mma_kernel(const float* __restrict__ down,
                  const int* __restrict__ iin, const int* __restrict__ iout)
{
    extern __shared__ __align__(16) float sm[];
    float* As = sm;
    float* Bs = sm + D_B_F;
    int*   iidx = (int*)(sm + D_IDX_F);
    int*   oidx = iidx + 128;

    const int tid = threadIdx.x, wid = tid >> 5, lane = tid & 31;
    const int g = lane >> 2, t4 = lane & 3;
    const int k = blockIdx.y;
    const int ebase = blockIdx.x * 128;
    const int nvalid = min(128, N_DOWN - ebase);

    const int* pin  = iin  + (size_t)k * N_DOWN + ebase;
    const int* pout = iout + (size_t)k * N_DOWN + ebase;
    if (tid < 128) {
        iidx[tid] = (tid < nvalid) ? pin[tid] : 0;
        oidx[tid] = (tid < nvalid) ? pout[tid] : -1;
    }
    __syncthreads();

    const int mbase = (wid & 3) * 32;
    const int nbase = (wid >> 2) * 64;
    const uint32_t* Ap = (const uint32_t*)As + (mbase + g) * D_HP + t4;
    const uint32_t* Bp = (const uint32_t*)Bs + (nbase + g) * D_HP + t4;
    const float* Wk = g_WdT + (size_t)k * C_DOWN * C_DOWN;

    float c[2][8][4] = {};

#pragma unroll
    for (int ph = 0; ph < 2; ph++) {
        // Gather A half: 2 threads/edge, 8 f4 each (cols ph*64 .. +63)
        {
            int e  = tid >> 1;
            int hh = tid & 1;
            if (e < nvalid) {
                const float4* src = (const float4*)(down + (size_t)iidx[e] * C_DOWN)
                                    + ph * 16 + hh * 8;
#pragma unroll
                for (int j = 0; j < 8; j++) {
                    float4 v = src[j];
                    v.x = to_tf32(v.x); v.y = to_tf32(v.y);
                    v.z = to_tf32(v.z); v.w = to_tf32(v.w);
                    *(float4*)&As[e * D_HP + (hh * 8 + j) * 4] = v;
                }
            } else {
                float4 z = make_float4(0.f, 0.f, 0.f, 0.f);
#pragma unroll
                for (int j = 0; j < 8; j++)
                    *(float4*)&As[e * D_HP + (hh * 8 + j) * 4] = z;
            }
        }
        // Stage B half: 128 rows x 16 f4 = 2048 f4, 8/thread
        {
#pragma unroll
            for (int j = 0; j < 8; j++) {
                int f = tid + j * 256;
                int n = f >> 4, t = f & 15;
                float4 v = *(const float4*)(Wk + (size_t)n * C_DOWN + ph * 64 + t * 4);
                *(float4*)&Bs[n * D_HP + t * 4] = v;
            }
        }
        __syncthreads();

#pragma unroll 4
        for (int s = 0; s < 8; s++) {
            const int kk = s * 8;
            uint32_t a[2][4];
#pragma unroll
            for (int mt = 0; mt < 2; mt++) {
                const uint32_t* p = Ap + mt * 16 * D_HP + kk;
                a[mt][0] = p[0]; a[mt][1] = p[8 * D_HP];
                a[mt][2] = p[4]; a[mt][3] = p[8 * D_HP + 4];
            }
#pragma unroll
            for (int j = 0; j < 8; j++) {
                const uint32_t* q = Bp + j * 8 * D_HP + kk;
                uint32_t b0 = q[0], b1 = q[4];
                mma_tf32(c[0][j], a[0], b0, b1);
                mma_tf32(c[1][j], a[1], b0, b1);
            }
        }
        __syncthreads();
    }

    // Stage D (stride 132) over the A+B region
#pragma unroll
    for (int mt = 0; mt < 2; mt++) {
        int row = mbase + mt * 16 + g;
#pragma unroll
        for (int j = 0; j < 8; j++) {
            int col = nbase + j * 8 + 2 * t4;
            *(float2*)&sm[row * D_DP + col]       = make_float2(c[mt][j][0], c[mt][j][1]);
            *(float2*)&sm[(row + 8) * D_DP + col] = make_float2(c[mt][j][2], c[mt][j][3]);
        }
    }
    __syncthreads();

    // Scatter: 4096 f4, 16/thread
#pragma unroll
    for (int t = 0; t < 16; t++) {
        int f = tid + t * 256;
        int e = f >> 5, q = f & 31;
        int o = oidx[e];
        if (o >= 0) {
            float4 v = *(float4*)&sm[e * D_DP + q * 4];
            red_add_v4(g_up + (size_t)o * C_DOWN + q * 4, v);
        }
    }
}

// ---------------------------------------------------------------------------
// Conv MMA: D[128,96] = relu_cat[128,192] @ WcT[k]^T, K split into 2 x 96.
// A half [128x100], B half [96x100] in SMEM (100 % 32 == 4). D at stride 100.
// 8 warps 4M x 2N (N=48). grid = (1250, 27), 256 threads, 2 CTAs/SM (90.6 KB).
// ---------------------------------------------------------------------------
#define C_HP   100
#define C_B_F  (128 * C_HP)                  // 12800
#define C_IDX_F (128 * C_HP + 96 * C_HP)     // 22400
#define C_SMEM  (C_IDX_F * 4 + 1024)

__global__ void __launch_bounds__(256, 2)
conv_mma_kernel(const float* __restrict__ skip,
                const int* __restrict__ iin, const int* __restrict__ iout,
                float* __restrict__ out)
{
    extern __shared__ __align__(16) float sm[];
    float* As = sm;
    float* Bs = sm + C_B_F;
    int*   iidx = (int*)(sm + C_IDX_F);
    int*   oidx = iidx + 128;

    const int tid = threadIdx.x, wid = tid >> 5, lane = tid & 31;
    const int g = lane >> 2, t4 = lane & 3;
    const int k = blockIdx.y;
    const int ebase = blockIdx.x * 128;

    const int* pin  = iin  + (size_t)k * N_UP + ebase;
    const int* pout = iout + (size_t)k * N_UP + ebase;
    if (tid < 128) {
        iidx[tid] = pin[tid];
        oidx[tid] = pout[tid];
    }
    __syncthreads();

    const int mbase = (wid & 3) * 32;
    const int nbase = (wid >> 2) * 48;
    const uint32_t* Ap = (const uint32_t*)As + (mbase + g) * C_HP + t4;
    const uint32_t* Bp = (const uint32_t*)Bs + (nbase + g) * C_HP + t4;
    const float* Wk = g_WcT + (size_t)k * C_OUT * C_CAT;

    float c[2][6][4] = {};

#pragma unroll
    for (int ph = 0; ph < 2; ph++) {
        // Gather A half (fused relu+concat): 2 threads/edge, 12 f4 each.
        // Global f4 index c4 = ph*24 + t; c4 < 32 -> relu(up), else skip.
        {
            int e  = tid >> 1;
            int hh = tid & 1;
            int src = iidx[e];
            const float4* up4 = (const float4*)(g_up + (size_t)src * C_DOWN);
            const float4* sk4 = (const float4*)(skip + (size_t)src * C_SKIP);
#pragma unroll
            for (int j = 0; j < 12; j++) {
                int t  = hh * 12 + j;
                int c4 = ph * 24 + t;
                float4 v;
                if (c4 < 32) {
                    v = up4[c4];
                    v.x = to_tf32(fmaxf(v.x, 0.f)); v.y = to_tf32(fmaxf(v.y, 0.f));
                    v.z = to_tf32(fmaxf(v.z, 0.f)); v.w = to_tf32(fmaxf(v.w, 0.f));
                } else {
                    v = sk4[c4 - 32];
                    v.x = to_tf32(v.x); v.y = to_tf32(v.y);
                    v.z = to_tf32(v.z); v.w = to_tf32(v.w);
                }
                *(float4*)&As[e * C_HP + t * 4] = v;
            }
        }
        // Stage B half: 96 rows x 24 f4 = 2304 f4, 9/thread
        {
#pragma unroll
            for (int j = 0; j < 9; j++) {
                int f = tid + j * 256;
                int n = f / 24, t = f % 24;
                float4 v = *(const float4*)(Wk + (size_t)n * C_CAT + ph * 96 + t * 4);
                *(float4*)&Bs[n * C_HP + t * 4] = v;
            }
        }
        __syncthreads();

#pragma unroll 4
        for (int s = 0; s < 12; s++) {
            const int kk = s * 8;
            uint32_t a[2][4];
#pragma unroll
            for (int mt = 0; mt < 2; mt++) {
                const uint32_t* p = Ap + mt * 16 * C_HP + kk;
                a[mt][0] = p[0]; a[mt][1] = p[8 * C_HP];
                a[mt][2] = p[4]; a[mt][3] = p[8 * C_HP + 4];
            }
#pragma unroll
            for (int j = 0; j < 6; j++) {
                const uint32_t* q = Bp + j * 8 * C_HP + kk;
                uint32_t b0 = q[0], b1 = q[4];
                mma_tf32(c[0][j], a[0], b0, b1);
                mma_tf32(c[1][j], a[1], b0, b1);
            }
        }
        __syncthreads();
    }

    // Stage D (stride 100) into A region
#pragma unroll
    for (int mt = 0; mt < 2; mt++) {
        int row = mbase + mt * 16 + g;
#pragma unroll
        for (int j = 0; j < 6; j++) {
            int col = nbase + j * 8 + 2 * t4;
            *(float2*)&sm[row * C_HP + col]       = make_float2(c[mt][j][0], c[mt][j][1]);
            *(float2*)&sm[(row + 8) * C_HP + col] = make_float2(c[mt][j][2], c[mt][j][3]);
        }
    }
    __syncthreads();

    // Scatter: 3072 f4, 12/thread
#pragma unroll
    for (int t = 0; t < 12; t++) {
        int f = tid + t * 256;
        int e = f / 24, q = f % 24;
        float4 v = *(float4*)&sm[e * C_HP + q * 4];
        red_add_v4(out + (size_t)oidx[e] * C_OUT + q * 4, v);
    }
}

// ---------------------------------------------------------------------------
// Final ReLU
// ---------------------------------------------------------------------------
__global__ void __launch_bounds__(256) relu_kernel(float4* __restrict__ out4) {
    int i = blockIdx.x * 256 + threadIdx.x;
    float4 v = out4[i];
    v.x = fmaxf(v.x, 0.f); v.y = fmaxf(v.y, 0.f);
    v.z = fmaxf(v.z, 0.f); v.w = fmaxf(v.w, 0.f);
    out4[i] = v;
}

// ---------------------------------------------------------------------------
// Launch
// ---------------------------------------------------------------------------
extern "C" void kernel_launch(void* const* d_in, const int* in_sizes, int n_in,
                              void* d_out, int out_size)
{
    const float* skip = nullptr; const float* down = nullptr;
    const float* Wd = nullptr;   const float* Wc = nullptr;
    const int *d_iin = nullptr, *d_iout = nullptr, *c_iin = nullptr, *c_iout = nullptr;

    for (int i = 0; i < n_in; i++) {
        int sz = in_sizes[i];
        if      (sz == N_UP * C_SKIP)         skip = (const float*)d_in[i];
        else if (sz == N_DOWN * C_DOWN)       down = (const float*)d_in[i];
        else if (sz == K27 * C_DOWN * C_DOWN) Wd   = (const float*)d_in[i];
        else if (sz == K27 * C_CAT * C_OUT)   Wc   = (const float*)d_in[i];
        else if (sz == K27 * N_DOWN) { if (!d_iin) d_iin = (const int*)d_in[i]; else d_iout = (const int*)d_in[i]; }
        else if (sz == K27 * N_UP)   { if (!c_iin) c_iin = (const int*)d_in[i]; else c_iout = (const int*)d_in[i]; }
    }
    float* out = (float*)d_out;

    cudaFuncSetAttribute(deconv_mma_kernel, cudaFuncAttributeMaxDynamicSharedMemorySize, D_SMEM);
    cudaFuncSetAttribute(conv_mma_kernel,   cudaFuncAttributeMaxDynamicSharedMemorySize, C_SMEM);

    zero_kernel<<<ZERO_F4 / 256, 256>>>((float4*)out);
    transpose_w_kernel<<<(WD_ELEMS + WC_ELEMS) / 256, 256>>>(Wd, Wc);
    deconv_mma_kernel<<<dim3((N_DOWN + 127) / 128, K27), 256, D_SMEM>>>(down, d_iin, d_iout);
    conv_mma_kernel<<<dim3(N_UP / 128, K27), 256, C_SMEM>>>(skip, c_iin, c_iout, out);
    relu_kernel<<<OUT_F4 / 256, 256>>>((float4*)out);
}

// round 6
// speedup vs baseline: 2.7613x; 1.3799x over previous
#include <cuda_runtime.h>
#include <cstdint>
#include <cstddef>

#define K27     27
#define N_DOWN  40000
#define N_UP    160000
#define C_DOWN  128
#define C_SKIP  64
#define C_CAT   192
#define C_OUT   96

// Scratch globals (no cudaMalloc allowed)
__device__ float g_up   [(size_t)N_UP * C_DOWN];           // 81.92 MB, fp32 accum -> relu+tf32
__device__ float g_downR[(size_t)N_DOWN * C_DOWN];         // tf32-RN rounded down_feat
__device__ float g_skipR[(size_t)N_UP * C_SKIP];           // tf32-RN rounded skip_feat
__device__ float g_WdT  [(size_t)K27 * C_DOWN * C_DOWN];   // W_deconv[k]^T [k][n][c], tf32-RN
__device__ float g_WcT  [(size_t)K27 * C_OUT  * C_CAT];    // W_conv[k]^T   [k][n][c], tf32-RN

// ---------------------------------------------------------------------------
// Helpers
// ---------------------------------------------------------------------------
__device__ __forceinline__ uint32_t smem_u32(const void* p) {
    uint32_t a;
    asm("{ .reg .u64 t; cvta.to.shared.u64 t, %1; cvt.u32.u64 %0, t; }" : "=r"(a) : "l"(p));
    return a;
}
__device__ __forceinline__ float to_tf32(float x) {
    float r;
    asm("cvt.rn.tf32.f32 %0, %1;" : "=f"(r) : "f"(x));
    return r;
}
__device__ __forceinline__ void red_add_v4(float* p, float4 v) {
    asm volatile("red.global.add.v4.f32 [%0], {%1, %2, %3, %4};"
                 :: "l"(p), "f"(v.x), "f"(v.y), "f"(v.z), "f"(v.w) : "memory");
}
__device__ __forceinline__ void mma_tf32(float* c, const uint32_t* a,
                                         uint32_t b0, uint32_t b1) {
    asm("mma.sync.aligned.m16n8k8.row.col.f32.tf32.tf32.f32 "
        "{%0,%1,%2,%3}, {%4,%5,%6,%7}, {%8,%9}, {%0,%1,%2,%3};"
        : "+f"(c[0]), "+f"(c[1]), "+f"(c[2]), "+f"(c[3])
        : "r"(a[0]), "r"(a[1]), "r"(a[2]), "r"(a[3]), "r"(b0), "r"(b1));
}
__device__ __forceinline__ void cp_async16(uint32_t dst, const float* src) {
    asm volatile("cp.async.cg.shared.global [%0], [%1], 16;" :: "r"(dst), "l"(src));
}
#define CP_COMMIT()  asm volatile("cp.async.commit_group;" ::: "memory")
#define CP_WAIT(n)   asm volatile("cp.async.wait_group %0;" :: "n"(n) : "memory")

// ---------------------------------------------------------------------------
// Prep kernels
// ---------------------------------------------------------------------------
#define UP_F4    ((N_UP * C_DOWN) / 4)     // 5,120,000
#define OUT_F4   ((N_UP * C_OUT) / 4)      // 3,840,000
#define ZERO_F4  (UP_F4 + OUT_F4)
#define DOWN_F4  ((N_DOWN * C_DOWN) / 4)   // 1,280,000
#define SKIP_F4  ((N_UP * C_SKIP) / 4)     // 2,560,000
#define RND_F4   (DOWN_F4 + SKIP_F4)       // 3,840,000

__global__ void __launch_bounds__(256) zero_kernel(float4* __restrict__ out4) {
    int i = blockIdx.x * 256 + threadIdx.x;
    float4 z = make_float4(0.f, 0.f, 0.f, 0.f);
    if (i < UP_F4) reinterpret_cast<float4*>(g_up)[i] = z;
    else           out4[i - UP_F4] = z;
}

__global__ void __launch_bounds__(256) round_inputs_kernel(
    const float4* __restrict__ down4, const float4* __restrict__ skip4)
{
    int i = blockIdx.x * 256 + threadIdx.x;       // grid exact = RND_F4/256
    if (i < DOWN_F4) {
        float4 v = down4[i];
        v.x = to_tf32(v.x); v.y = to_tf32(v.y); v.z = to_tf32(v.z); v.w = to_tf32(v.w);
        reinterpret_cast<float4*>(g_downR)[i] = v;
    } else {
        int j = i - DOWN_F4;
        float4 v = skip4[j];
        v.x = to_tf32(v.x); v.y = to_tf32(v.y); v.z = to_tf32(v.z); v.w = to_tf32(v.w);
        reinterpret_cast<float4*>(g_skipR)[j] = v;
    }
}

// relu + tf32-RN round g_up in place (between deconv and conv)
__global__ void __launch_bounds__(256) relu_round_up_kernel() {
    int i = blockIdx.x * 256 + threadIdx.x;       // grid exact = UP_F4/256
    float4 v = reinterpret_cast<float4*>(g_up)[i];
    v.x = to_tf32(fmaxf(v.x, 0.f)); v.y = to_tf32(fmaxf(v.y, 0.f));
    v.z = to_tf32(fmaxf(v.z, 0.f)); v.w = to_tf32(fmaxf(v.w, 0.f));
    reinterpret_cast<float4*>(g_up)[i] = v;
}

#define WD_ELEMS (K27 * C_DOWN * C_DOWN)
#define WC_ELEMS (K27 * C_OUT * C_CAT)
__global__ void __launch_bounds__(256) transpose_w_kernel(
    const float* __restrict__ Wd, const float* __restrict__ Wc)
{
    int i = blockIdx.x * 256 + threadIdx.x;
    if (i < WD_ELEMS) {
        int k = i / (C_DOWN * C_DOWN), r = i % (C_DOWN * C_DOWN);
        int n = r / C_DOWN, c = r % C_DOWN;
        g_WdT[i] = to_tf32(Wd[((size_t)k * C_DOWN + c) * C_DOWN + n]);
    } else {
        int j = i - WD_ELEMS;
        int k = j / (C_OUT * C_CAT), r = j % (C_OUT * C_CAT);
        int n = r / C_CAT, c = r % C_CAT;
        g_WcT[j] = to_tf32(Wc[((size_t)k * C_CAT + c) * C_OUT + n]);
    }
}

// ---------------------------------------------------------------------------
// Deconv MMA: D[128,128] = A[128,128] @ WdT[k]^T. 4 K-phases of 32,
// double-buffered cp.async. Strides 36 (%8==4, conflict-free). D at 132.
// 8 warps 4M x 2N. grid=(313,27), 256 thr, 2 CTAs/SM (75 KB).
// ---------------------------------------------------------------------------
#define D_S     36
#define D_AB_F  (128 * D_S)                        // 4608
#define D_BB_F  (128 * D_S)                        // 4608
#define D_IDX_F (2 * D_AB_F + 2 * D_BB_F)          // 18432
#define D_DP    132
#define D_SMEM  ((D_IDX_F + 256) * 4)

__device__ __forceinline__ void deconv_issue(uint32_t aBuf, uint32_t bBuf, int p,
                                             const int* iidx, const float* Wk, int tid)
{
#pragma unroll
    for (int i = 0; i < 4; i++) {                  // A: 1024 chunks
        int ch = tid + i * 256;
        int e = ch >> 3, sub = ch & 7;
        const float* src = g_downR + (size_t)iidx[e] * C_DOWN + (p * 8 + sub) * 4;
        cp_async16(aBuf + (e * D_S + sub * 4) * 4, src);
    }
#pragma unroll
    for (int i = 0; i < 4; i++) {                  // B: 1024 chunks
        int ch = tid + i * 256;
        int n = ch >> 3, sub = ch & 7;
        const float* src = Wk + (size_t)n * C_DOWN + p * 32 + sub * 4;
        cp_async16(bBuf + (n * D_S + sub * 4) * 4, src);
    }
    CP_COMMIT();
}

__global__ void __launch_bounds__(256, 2)
deconv_mma_kernel(const int* __restrict__ iin, const int* __restrict__ iout)
{
    extern __shared__ __align__(16) float sm[];
    const uint32_t sbase = smem_u32(sm);
    const uint32_t aB[2] = { sbase, sbase + D_AB_F * 4 };
    const uint32_t bB[2] = { sbase + 2 * D_AB_F * 4, sbase + (2 * D_AB_F + D_BB_F) * 4 };
    int* iidx = (int*)(sm + D_IDX_F);
    int* oidx = iidx + 128;

    const int tid = threadIdx.x, wid = tid >> 5, lane = tid & 31;
    const int g = lane >> 2, t4 = lane & 3;
    const int k = blockIdx.y;
    const int ebase = blockIdx.x * 128;
    const int nvalid = min(128, N_DOWN - ebase);

    const int* pin  = iin  + (size_t)k * N_DOWN + ebase;
    const int* pout = iout + (size_t)k * N_DOWN + ebase;
    if (tid < 128) {
        iidx[tid] = (tid < nvalid) ? pin[tid] : pin[0];
        oidx[tid] = (tid < nvalid) ? pout[tid] : -1;
    }
    __syncthreads();

    const float* Wk = g_WdT + (size_t)k * C_DOWN * C_DOWN;
    const int mbase = (wid & 3) * 32;
    const int nbase = (wid >> 2) * 64;

    deconv_issue(aB[0], bB[0], 0, iidx, Wk, tid);

    float c[2][8][4] = {};
#pragma unroll
    for (int p = 0; p < 4; p++) {
        if (p < 3) deconv_issue(aB[(p + 1) & 1], bB[(p + 1) & 1], p + 1, iidx, Wk, tid);
        if (p < 3) CP_WAIT(1); else CP_WAIT(0);
        __syncthreads();

        const uint32_t* Ap = (const uint32_t*)sm + (p & 1) * D_AB_F + (mbase + g) * D_S + t4;
        const uint32_t* Bp = (const uint32_t*)sm + 2 * D_AB_F + (p & 1) * D_BB_F
                             + (nbase + g) * D_S + t4;
#pragma unroll
        for (int s = 0; s < 4; s++) {
            const int kk = s * 8;
            uint32_t a[2][4];
#pragma unroll
            for (int mt = 0; mt < 2; mt++) {
                const uint32_t* pA = Ap + mt * 16 * D_S + kk;
                a[mt][0] = pA[0]; a[mt][1] = pA[8 * D_S];
                a[mt][2] = pA[4]; a[mt][3] = pA[8 * D_S + 4];
            }
#pragma unroll
            for (int j = 0; j < 8; j++) {
                const uint32_t* q = Bp + j * 8 * D_S + kk;
                uint32_t b0 = q[0], b1 = q[4];
                mma_tf32(c[0][j], a[0], b0, b1);
                mma_tf32(c[1][j], a[1], b0, b1);
            }
        }
        __syncthreads();
    }

    // Stage D (stride 132) over buffer region
#pragma unroll
    for (int mt = 0; mt < 2; mt++) {
        int row = mbase + mt * 16 + g;
#pragma unroll
        for (int j = 0; j < 8; j++) {
            int col = nbase + j * 8 + 2 * t4;
            *(float2*)&sm[row * D_DP + col]       = make_float2(c[mt][j][0], c[mt][j][1]);
            *(float2*)&sm[(row + 8) * D_DP + col] = make_float2(c[mt][j][2], c[mt][j][3]);
        }
    }
    __syncthreads();

    // Scatter: 4096 f4, 16/thread
#pragma unroll
    for (int t = 0; t < 16; t++) {
        int f = tid + t * 256;
        int e = f >> 5, q = f & 31;
        int o = oidx[e];
        if (o >= 0) {
            float4 v = *(float4*)&sm[e * D_DP + q * 4];
            red_add_v4(g_up + (size_t)o * C_DOWN + q * 4, v);
        }
    }
}

// ---------------------------------------------------------------------------
// Conv MMA: D[128,96] = relu_cat[128,192] @ WcT[k]^T. 4 K-phases of 48,
// double-buffered cp.async (A from relu+rounded g_up / g_skipR). Stride 52.
// D at stride 100. 8 warps 4M x 2N. grid=(1250,27), 256 thr, 2 CTAs/SM (94 KB).
// ---------------------------------------------------------------------------
#define C_S     52
#define C_AB_F  (128 * C_S)                        // 6656
#define C_BB_F  (96 * C_S)                         // 4992
#define C_IDX_F (2 * C_AB_F + 2 * C_BB_F)          // 23296
#define C_DP    100
#define C_SMEM  ((C_IDX_F + 256) * 4)

__device__ __forceinline__ void conv_issue(uint32_t aBuf, uint32_t bBuf, int p,
                                           const int* iidx, const float* Wk, int tid)
{
#pragma unroll
    for (int i = 0; i < 6; i++) {                  // A: 1536 chunks
        int ch = tid + i * 256;
        int e = ch / 12, sub = ch % 12;
        int f4g = p * 12 + sub;
        int row = iidx[e];
        const float* src = (f4g < 32)
            ? g_up   + (size_t)row * C_DOWN + f4g * 4
            : g_skipR + (size_t)row * C_SKIP + (f4g - 32) * 4;
        cp_async16(aBuf + (e * C_S + sub * 4) * 4, src);
    }
#pragma unroll
    for (int i = 0; i < 5; i++) {                  // B: 1152 chunks
        int ch = tid + i * 256;
        if (ch < 1152) {
            int n = ch / 12, sub = ch % 12;
            const float* src = Wk + (size_t)n * C_CAT + p * 48 + sub * 4;
            cp_async16(bBuf + (n * C_S + sub * 4) * 4, src);
        }
    }
    CP_COMMIT();
}

__global__ void __launch_bounds__(256, 2)
conv_mma_kernel(const int* __restrict__ iin, const int* __restrict__ iout,
                float* __restrict__ out)
{
    extern __shared__ __align__(16) float sm[];
    const uint32_t sbase = smem_u32(sm);
    const uint32_t aB[2] = { sbase, sbase + C_AB_F * 4 };
    const uint32_t bB[2] = { sbase + 2 * C_AB_F * 4, sbase + (2 * C_AB_F + C_BB_F) * 4 };
    int* iidx = (int*)(sm + C_IDX_F);
    int* oidx = iidx + 128;

    const int tid = threadIdx.x, wid = tid >> 5, lane = tid & 31;
    const int g = lane >> 2, t4 = lane & 3;
    const int k = blockIdx.y;
    const int ebase = blockIdx.x * 128;

    const int* pin  = iin  + (size_t)k * N_UP + ebase;
    const int* pout = iout + (size_t)k * N_UP + ebase;
    if (tid < 128) {
        iidx[tid] = pin[tid];
        oidx[tid] = pout[tid];
    }
    __syncthreads();

    const float* Wk = g_WcT + (size_t)k * C_OUT * C_CAT;
    const int mbase = (wid & 3) * 32;
    const int nbase = (wid >> 2) * 48;

    conv_issue(aB[0], bB[0], 0, iidx, Wk, tid);

    float c[2][6][4] = {};
#pragma unroll
    for (int p = 0; p < 4; p++) {
        if (p < 3) conv_issue(aB[(p + 1) & 1], bB[(p + 1) & 1], p + 1, iidx, Wk, tid);
        if (p < 3) CP_WAIT(1); else CP_WAIT(0);
        __syncthreads();

        const uint32_t* Ap = (const uint32_t*)sm + (p & 1) * C_AB_F + (mbase + g) * C_S + t4;
        const uint32_t* Bp = (const uint32_t*)sm + 2 * C_AB_F + (p & 1) * C_BB_F
                             + (nbase + g) * C_S + t4;
#pragma unroll
        for (int s = 0; s < 6; s++) {
            const int kk = s * 8;
            uint32_t a[2][4];
#pragma unroll
            for (int mt = 0; mt < 2; mt++) {
                const uint32_t* pA = Ap + mt * 16 * C_S + kk;
                a[mt][0] = pA[0]; a[mt][1] = pA[8 * C_S];
                a[mt][2] = pA[4]; a[mt][3] = pA[8 * C_S + 4];
            }
#pragma unroll
            for (int j = 0; j < 6; j++) {
                const uint32_t* q = Bp + j * 8 * C_S + kk;
                uint32_t b0 = q[0], b1 = q[4];
                mma_tf32(c[0][j], a[0], b0, b1);
                mma_tf32(c[1][j], a[1], b0, b1);
            }
        }
        __syncthreads();
    }

    // Stage D (stride 100) over buffer region
#pragma unroll
    for (int mt = 0; mt < 2; mt++) {
        int row = mbase + mt * 16 + g;
#pragma unroll
        for (int j = 0; j < 6; j++) {
            int col = nbase + j * 8 + 2 * t4;
            *(float2*)&sm[row * C_DP + col]       = make_float2(c[mt][j][0], c[mt][j][1]);
            *(float2*)&sm[(row + 8) * C_DP + col] = make_float2(c[mt][j][2], c[mt][j][3]);
        }
    }
    __syncthreads();

    // Scatter: 3072 f4, 12/thread
#pragma unroll
    for (int t = 0; t < 12; t++) {
        int f = tid + t * 256;
        int e = f / 24, q = f % 24;
        float4 v = *(float4*)&sm[e * C_DP + q * 4];
        red_add_v4(out + (size_t)oidx[e] * C_OUT + q * 4, v);
    }
}

// ---------------------------------------------------------------------------
// Final ReLU
// ---------------------------------------------------------------------------
__global__ void __launch_bounds__(256) relu_kernel(float4* __restrict__ out4) {
    int i = blockIdx.x * 256 + threadIdx.x;
    float4 v = out4[i];
    v.x = fmaxf(v.x, 0.f); v.y = fmaxf(v.y, 0.f);
    v.z = fmaxf(v.z, 0.f); v.w = fmaxf(v.w, 0.f);
    out4[i] = v;
}

// ---------------------------------------------------------------------------
// Launch
// ---------------------------------------------------------------------------
extern "C" void kernel_launch(void* const* d_in, const int* in_sizes, int n_in,
                              void* d_out, int out_size)
{
    const float* skip = nullptr; const float* down = nullptr;
    const float* Wd = nullptr;   const float* Wc = nullptr;
    const int *d_iin = nullptr, *d_iout = nullptr, *c_iin = nullptr, *c_iout = nullptr;

    for (int i = 0; i < n_in; i++) {
        int sz = in_sizes[i];
        if      (sz == N_UP * C_SKIP)         skip = (const float*)d_in[i];
        else if (sz == N_DOWN * C_DOWN)       down = (const float*)d_in[i];
        else if (sz == K27 * C_DOWN * C_DOWN) Wd   = (const float*)d_in[i];
        else if (sz == K27 * C_CAT * C_OUT)   Wc   = (const float*)d_in[i];
        else if (sz == K27 * N_DOWN) { if (!d_iin) d_iin = (const int*)d_in[i]; else d_iout = (const int*)d_in[i]; }
        else if (sz == K27 * N_UP)   { if (!c_iin) c_iin = (const int*)d_in[i]; else c_iout = (const int*)d_in[i]; }
    }
    float* out = (float*)d_out;

    cudaFuncSetAttribute(deconv_mma_kernel, cudaFuncAttributeMaxDynamicSharedMemorySize, D_SMEM);
    cudaFuncSetAttribute(conv_mma_kernel,   cudaFuncAttributeMaxDynamicSharedMemorySize, C_SMEM);

    zero_kernel<<<ZERO_F4 / 256, 256>>>((float4*)out);
    transpose_w_kernel<<<(WD_ELEMS + WC_ELEMS) / 256, 256>>>(Wd, Wc);
    round_inputs_kernel<<<RND_F4 / 256, 256>>>((const float4*)down, (const float4*)skip);
    deconv_mma_kernel<<<dim3((N_DOWN + 127) / 128, K27), 256, D_SMEM>>>(d_iin, d_iout);
    relu_round_up_kernel<<<UP_F4 / 256, 256>>>();
    conv_mma_kernel<<<dim3(N_UP / 128, K27), 256, C_SMEM>>>(c_iin, c_iout, out);
    relu_kernel<<<OUT_F4 / 256, 256>>>((float4*)out);
}

// round 7
// speedup vs baseline: 3.0219x; 1.0944x over previous
#include <cuda_runtime.h>
#include <cstdint>
#include <cstddef>

#define K27     27
#define N_DOWN  40000
#define N_UP    160000
#define C_DOWN  128
#define C_SKIP  64
#define C_CAT   192
#define C_OUT   96

// Scratch globals (no cudaMalloc allowed)
// K-pair permutation tau: within each 8-group, stored pos (2j)->ch j, (2j+1)->ch j+4.
__device__ float g_up   [(size_t)N_UP * C_DOWN];           // deconv out; cols tau-permuted
__device__ float g_downR[(size_t)N_DOWN * C_DOWN];         // tf32-RN, tau-permuted channels
__device__ float g_skipR[(size_t)N_UP * C_SKIP];           // tf32-RN, tau-permuted channels
__device__ float g_WdT  [(size_t)K27 * C_DOWN * C_DOWN];   // [k][n][p] = Wd[k][tau(p)][tau(n)]
__device__ float g_WcT  [(size_t)K27 * C_OUT  * C_CAT];    // [k][n][p] = Wc[k][tau(p)][n]

// ---------------------------------------------------------------------------
// Helpers
// ---------------------------------------------------------------------------
__device__ __forceinline__ uint32_t smem_u32(const void* p) {
    uint32_t a;
    asm("{ .reg .u64 t; cvta.to.shared.u64 t, %1; cvt.u32.u64 %0, t; }" : "=r"(a) : "l"(p));
    return a;
}
__device__ __forceinline__ float to_tf32(float x) {
    float r;
    asm("cvt.rn.tf32.f32 %0, %1;" : "=f"(r) : "f"(x));
    return r;
}
__device__ __forceinline__ int tau(int p) {       // stored pos -> channel
    int j = p & 7, b = p & ~7;
    return b + ((j & 1) ? (j >> 1) + 4 : (j >> 1));
}
__device__ __forceinline__ void red_add_v4(float* p, float4 v) {
    asm volatile("red.global.add.v4.f32 [%0], {%1, %2, %3, %4};"
                 :: "l"(p), "f"(v.x), "f"(v.y), "f"(v.z), "f"(v.w) : "memory");
}
__device__ __forceinline__ void mma_tf32(float* c, float2 a01, float2 a23,
                                         float2 b01) {
    asm("mma.sync.aligned.m16n8k8.row.col.f32.tf32.tf32.f32 "
        "{%0,%1,%2,%3}, {%4,%5,%6,%7}, {%8,%9}, {%0,%1,%2,%3};"
        : "+f"(c[0]), "+f"(c[1]), "+f"(c[2]), "+f"(c[3])
        : "r"(__float_as_uint(a01.x)), "r"(__float_as_uint(a23.x)),
          "r"(__float_as_uint(a01.y)), "r"(__float_as_uint(a23.y)),
          "r"(__float_as_uint(b01.x)), "r"(__float_as_uint(b01.y)));
}
__device__ __forceinline__ void cp_async16(uint32_t dst, const float* src) {
    asm volatile("cp.async.cg.shared.global [%0], [%1], 16;" :: "r"(dst), "l"(src));
}
#define CP_COMMIT()  asm volatile("cp.async.commit_group;" ::: "memory")
#define CP_WAIT(n)   asm volatile("cp.async.wait_group %0;" :: "n"(n) : "memory")

// ---------------------------------------------------------------------------
// Prep kernels
// ---------------------------------------------------------------------------
#define UP_F4    ((N_UP * C_DOWN) / 4)
#define OUT_F4   ((N_UP * C_OUT) / 4)
#define ZERO_F4  (UP_F4 + OUT_F4)
#define DOWN_F8  ((N_DOWN * C_DOWN) / 8)   // 640,000
#define SKIP_F8  ((N_UP * C_SKIP) / 8)     // 1,280,000
#define RND_F8   (DOWN_F8 + SKIP_F8)       // 1,920,000

__global__ void __launch_bounds__(256) zero_kernel(float4* __restrict__ out4) {
    int i = blockIdx.x * 256 + threadIdx.x;
    float4 z = make_float4(0.f, 0.f, 0.f, 0.f);
    if (i < UP_F4) reinterpret_cast<float4*>(g_up)[i] = z;
    else           out4[i - UP_F4] = z;
}

// Round + tau-permute inputs: out 8-group (o0..o7) from in (i0..i7):
// o[2j] = i[j], o[2j+1] = i[j+4].
__global__ void __launch_bounds__(256) round_inputs_kernel(
    const float4* __restrict__ down4, const float4* __restrict__ skip4)
{
    int i = blockIdx.x * 256 + threadIdx.x;       // grid exact = RND_F8/256
    const float4* src4; float4* dst4; int g8;
    if (i < DOWN_F8) { src4 = down4; dst4 = (float4*)g_downR; g8 = i; }
    else             { src4 = skip4; dst4 = (float4*)g_skipR; g8 = i - DOWN_F8; }
    float4 a = src4[2 * g8], b = src4[2 * g8 + 1];
    float4 o0 = make_float4(to_tf32(a.x), to_tf32(b.x), to_tf32(a.y), to_tf32(b.y));
    float4 o1 = make_float4(to_tf32(a.z), to_tf32(b.z), to_tf32(a.w), to_tf32(b.w));
    dst4[2 * g8]     = o0;
    dst4[2 * g8 + 1] = o1;
}

// relu + tf32-RN round g_up in place (already tau-ordered via WdT's n-perm)
__global__ void __launch_bounds__(256) relu_round_up_kernel() {
    int i = blockIdx.x * 256 + threadIdx.x;
    float4 v = reinterpret_cast<float4*>(g_up)[i];
    v.x = to_tf32(fmaxf(v.x, 0.f)); v.y = to_tf32(fmaxf(v.y, 0.f));
    v.z = to_tf32(fmaxf(v.z, 0.f)); v.w = to_tf32(fmaxf(v.w, 0.f));
    reinterpret_cast<float4*>(g_up)[i] = v;
}

#define WD_ELEMS (K27 * C_DOWN * C_DOWN)
#define WC_ELEMS (K27 * C_OUT * C_CAT)
__global__ void __launch_bounds__(256) transpose_w_kernel(
    const float* __restrict__ Wd, const float* __restrict__ Wc)
{
    int i = blockIdx.x * 256 + threadIdx.x;
    if (i < WD_ELEMS) {
        int k = i / (C_DOWN * C_DOWN), r = i % (C_DOWN * C_DOWN);
        int n = r / C_DOWN, p = r % C_DOWN;
        g_WdT[i] = to_tf32(Wd[((size_t)k * C_DOWN + tau(p)) * C_DOWN + tau(n)]);
    } else {
        int j = i - WD_ELEMS;
        int k = j / (C_OUT * C_CAT), r = j % (C_OUT * C_CAT);
        int n = r / C_CAT, p = r % C_CAT;
        g_WcT[j] = to_tf32(Wc[((size_t)k * C_CAT + tau(p)) * C_OUT + n]);
    }
}

// ---------------------------------------------------------------------------
// Deconv MMA: D[128,128] = A[128,128] @ WdT[k]^T. 4 K-phases of 32,
// double-buffered cp.async. Stride 40 (%32==8 -> conflict-free LDS.64).
// D staged at stride 132. 8 warps 4M x 2N. grid=(313,27), 2 CTAs/SM (82 KB).
// ---------------------------------------------------------------------------
#define D_S     40
#define D_AB_F  (128 * D_S)                        // 5120
#define D_BB_F  (128 * D_S)                        // 5120
#define D_IDX_F (2 * D_AB_F + 2 * D_BB_F)          // 20480
#define D_DP    132
#define D_SMEM  ((D_IDX_F + 256) * 4)

__device__ __forceinline__ void deconv_issue(uint32_t aBuf, uint32_t bBuf, int p,
                                             const int* iidx, const float* Wk, int tid)
{
#pragma unroll
    for (int i = 0; i < 4; i++) {                  // A: 1024 chunks
        int ch = tid + i * 256;
        int e = ch >> 3, sub = ch & 7;
        const float* src = g_downR + (size_t)iidx[e] * C_DOWN + p * 32 + sub * 4;
        cp_async16(aBuf + (e * D_S + sub * 4) * 4, src);
    }
#pragma unroll
    for (int i = 0; i < 4; i++) {                  // B: 1024 chunks
        int ch = tid + i * 256;
        int n = ch >> 3, sub = ch & 7;
        const float* src = Wk + (size_t)n * C_DOWN + p * 32 + sub * 4;
        cp_async16(bBuf + (n * D_S + sub * 4) * 4, src);
    }
    CP_COMMIT();
}

__global__ void __launch_bounds__(256, 2)
deconv_mma_kernel(const int* __restrict__ iin, const int* __restrict__ iout)
{
    extern __shared__ __align__(16) float sm[];
    const uint32_t sbase = smem_u32(sm);
    const uint32_t aB[2] = { sbase, sbase + D_AB_F * 4 };
    const uint32_t bB[2] = { sbase + 2 * D_AB_F * 4, sbase + (2 * D_AB_F + D_BB_F) * 4 };
    int* iidx = (int*)(sm + D_IDX_F);
    int* oidx = iidx + 128;

    const int tid = threadIdx.x, wid = tid >> 5, lane = tid & 31;
    const int g = lane >> 2, t4 = lane & 3;
    const int k = blockIdx.y;
    const int ebase = blockIdx.x * 128;
    const int nvalid = min(128, N_DOWN - ebase);

    const int* pin  = iin  + (size_t)k * N_DOWN + ebase;
    const int* pout = iout + (size_t)k * N_DOWN + ebase;
    if (tid < 128) {
        iidx[tid] = (tid < nvalid) ? pin[tid] : pin[0];
        oidx[tid] = (tid < nvalid) ? pout[tid] : -1;
    }
    __syncthreads();

    const float* Wk = g_WdT + (size_t)k * C_DOWN * C_DOWN;
    const int mbase = (wid & 3) * 32;
    const int nbase = (wid >> 2) * 64;

    deconv_issue(aB[0], bB[0], 0, iidx, Wk, tid);

    float c[2][8][4] = {};
#pragma unroll
    for (int p = 0; p < 4; p++) {
        if (p < 3) deconv_issue(aB[(p + 1) & 1], bB[(p + 1) & 1], p + 1, iidx, Wk, tid);
        if (p < 3) CP_WAIT(1); else CP_WAIT(0);
        __syncthreads();

        const float* Ab = sm + (p & 1) * D_AB_F + (mbase + g) * D_S + 2 * t4;
        const float* Bb = sm + 2 * D_AB_F + (p & 1) * D_BB_F + (nbase + g) * D_S + 2 * t4;
#pragma unroll
        for (int s = 0; s < 4; s++) {
            const int kk = s * 8;
            float2 a01[2], a23[2];
#pragma unroll
            for (int mt = 0; mt < 2; mt++) {
                a01[mt] = *(const float2*)(Ab + mt * 16 * D_S + kk);
                a23[mt] = *(const float2*)(Ab + (mt * 16 + 8) * D_S + kk);
            }
#pragma unroll
            for (int j = 0; j < 8; j++) {
                float2 b01 = *(const float2*)(Bb + j * 8 * D_S + kk);
                mma_tf32(c[0][j], a01[0], a23[0], b01);
                mma_tf32(c[1][j], a01[1], a23[1], b01);
            }
        }
        __syncthreads();
    }

    // Stage D (stride 132) over buffer region
#pragma unroll
    for (int mt = 0; mt < 2; mt++) {
        int row = mbase + mt * 16 + g;
#pragma unroll
        for (int j = 0; j < 8; j++) {
            int col = nbase + j * 8 + 2 * t4;
            *(float2*)&sm[row * D_DP + col]       = make_float2(c[mt][j][0], c[mt][j][1]);
            *(float2*)&sm[(row + 8) * D_DP + col] = make_float2(c[mt][j][2], c[mt][j][3]);
        }
    }
    __syncthreads();

    // Scatter: 4096 f4, 16/thread
#pragma unroll
    for (int t = 0; t < 16; t++) {
        int f = tid + t * 256;
        int e = f >> 5, q = f & 31;
        int o = oidx[e];
        if (o >= 0) {
            float4 v = *(float4*)&sm[e * D_DP + q * 4];
            red_add_v4(g_up + (size_t)o * C_DOWN + q * 4, v);
        }
    }
}

// ---------------------------------------------------------------------------
// Conv MMA: D[128,96] = relu_cat[128,192] @ WcT[k]^T. 6 K-phases of 32,
// double-buffered cp.async. Stride 40. Phases 0-3 from g_up, 4-5 from g_skipR.
// D staged at stride 100. 8 warps 4M x 2N. grid=(1250,27), 2 CTAs/SM (72 KB).
// ---------------------------------------------------------------------------
#define C_S     40
#define C_AB_F  (128 * C_S)                        // 5120
#define C_BB_F  (96 * C_S)                         // 3840
#define C_IDX_F (2 * C_AB_F + 2 * C_BB_F)          // 17920
#define C_DP    100
#define C_SMEM  ((C_IDX_F + 256) * 4)

__device__ __forceinline__ void conv_issue(uint32_t aBuf, uint32_t bBuf, int p,
                                           const int* iidx, const float* Wk, int tid)
{
#pragma unroll
    for (int i = 0; i < 4; i++) {                  // A: 1024 chunks
        int ch = tid + i * 256;
        int e = ch >> 3, sub = ch & 7;
        int row = iidx[e];
        const float* src = (p < 4)
            ? g_up    + (size_t)row * C_DOWN + p * 32 + sub * 4
            : g_skipR + (size_t)row * C_SKIP + (p - 4) * 32 + sub * 4;
        cp_async16(aBuf + (e * C_S + sub * 4) * 4, src);
    }
#pragma unroll
    for (int i = 0; i < 3; i++) {                  // B: 768 chunks
        int ch = tid + i * 256;
        int n = ch >> 3, sub = ch & 7;
        const float* src = Wk + (size_t)n * C_CAT + p * 32 + sub * 4;
        cp_async16(bBuf + (n * C_S + sub * 4) * 4, src);
    }
    CP_COMMIT();
}

__global__ void __launch_bounds__(256, 2)
conv_mma_kernel(const int* __restrict__ iin, const int* __restrict__ iout,
                float* __restrict__ out)
{
    extern __shared__ __align__(16) float sm[];
    const uint32_t sbase = smem_u32(sm);
    const uint32_t aB[2] = { sbase, sbase + C_AB_F * 4 };
    const uint32_t bB[2] = { sbase + 2 * C_AB_F * 4, sbase + (2 * C_AB_F + C_BB_F) * 4 };
    int* iidx = (int*)(sm + C_IDX_F);
    int* oidx = iidx + 128;

    const int tid = threadIdx.x, wid = tid >> 5, lane = tid & 31;
    const int g = lane >> 2, t4 = lane & 3;
    const int k = blockIdx.y;
    const int ebase = blockIdx.x * 128;

    const int* pin  = iin  + (size_t)k * N_UP + ebase;
    const int* pout = iout + (size_t)k * N_UP + ebase;
    if (tid < 128) {
        iidx[tid] = pin[tid];
        oidx[tid] = pout[tid];
    }
    __syncthreads();

    const float* Wk = g_WcT + (size_t)k * C_OUT * C_CAT;
    const int mbase = (wid & 3) * 32;
    const int nbase = (wid >> 2) * 48;

    conv_issue(aB[0], bB[0], 0, iidx, Wk, tid);

    float c[2][6][4] = {};
#pragma unroll
    for (int p = 0; p < 6; p++) {
        if (p < 5) conv_issue(aB[(p + 1) & 1], bB[(p + 1) & 1], p + 1, iidx, Wk, tid);
        if (p < 5) CP_WAIT(1); else CP_WAIT(0);
        __syncthreads();

        const float* Ab = sm + (p & 1) * C_AB_F + (mbase + g) * C_S + 2 * t4;
        const float* Bb = sm + 2 * C_AB_F + (p & 1) * C_BB_F + (nbase + g) * C_S + 2 * t4;
#pragma unroll
        for (int s = 0; s < 4; s++) {
            const int kk = s * 8;
            float2 a01[2], a23[2];
#pragma unroll
            for (int mt = 0; mt < 2; mt++) {
                a01[mt] = *(const float2*)(Ab + mt * 16 * C_S + kk);
                a23[mt] = *(const float2*)(Ab + (mt * 16 + 8) * C_S + kk);
            }
#pragma unroll
            for (int j = 0; j < 6; j++) {
                float2 b01 = *(const float2*)(Bb + j * 8 * C_S + kk);
                mma_tf32(c[0][j], a01[0], a23[0], b01);
                mma_tf32(c[1][j], a01[1], a23[1], b01);
            }
        }
        __syncthreads();
    }

    // Stage D (stride 100) over buffer region
#pragma unroll
    for (int mt = 0; mt < 2; mt++) {
        int row = mbase + mt * 16 + g;
#pragma unroll
        for (int j = 0; j < 6; j++) {
            int col = nbase + j * 8 + 2 * t4;
            *(float2*)&sm[row * C_DP + col]       = make_float2(c[mt][j][0], c[mt][j][1]);
            *(float2*)&sm[(row + 8) * C_DP + col] = make_float2(c[mt][j][2], c[mt][j][3]);
        }
    }
    __syncthreads();

    // Scatter: 3072 f4, 12/thread
#pragma unroll
    for (int t = 0; t < 12; t++) {
        int f = tid + t * 256;
        int e = f / 24, q = f % 24;
        float4 v = *(float4*)&sm[e * C_DP + q * 4];
        red_add_v4(out + (size_t)oidx[e] * C_OUT + q * 4, v);
    }
}

// ---------------------------------------------------------------------------
// Final ReLU
// ---------------------------------------------------------------------------
__global__ void __launch_bounds__(256) relu_kernel(float4* __restrict__ out4) {
    int i = blockIdx.x * 256 + threadIdx.x;
    float4 v = out4[i];
    v.x = fmaxf(v.x, 0.f); v.y = fmaxf(v.y, 0.f);
    v.z = fmaxf(v.z, 0.f); v.w = fmaxf(v.w, 0.f);
    out4[i] = v;
}

// ---------------------------------------------------------------------------
// Launch
// ---------------------------------------------------------------------------
extern "C" void kernel_launch(void* const* d_in, const int* in_sizes, int n_in,
                              void* d_out, int out_size)
{
    const float* skip = nullptr; const float* down = nullptr;
    const float* Wd = nullptr;   const float* Wc = nullptr;
    const int *d_iin = nullptr, *d_iout = nullptr, *c_iin = nullptr, *c_iout = nullptr;

    for (int i = 0; i < n_in; i++) {
        int sz = in_sizes[i];
        if      (sz == N_UP * C_SKIP)         skip = (const float*)d_in[i];
        else if (sz == N_DOWN * C_DOWN)       down = (const float*)d_in[i];
        else if (sz == K27 * C_DOWN * C_DOWN) Wd   = (const float*)d_in[i];
        else if (sz == K27 * C_CAT * C_OUT)   Wc   = (const float*)d_in[i];
        else if (sz == K27 * N_DOWN) { if (!d_iin) d_iin = (const int*)d_in[i]; else d_iout = (const int*)d_in[i]; }
        else if (sz == K27 * N_UP)   { if (!c_iin) c_iin = (const int*)d_in[i]; else c_iout = (const int*)d_in[i]; }
    }
    float* out = (float*)d_out;

    cudaFuncSetAttribute(deconv_mma_kernel, cudaFuncAttributeMaxDynamicSharedMemorySize, D_SMEM);
    cudaFuncSetAttribute(conv_mma_kernel,   cudaFuncAttributeMaxDynamicSharedMemorySize, C_SMEM);

    zero_kernel<<<ZERO_F4 / 256, 256>>>((float4*)out);
    transpose_w_kernel<<<(WD_ELEMS + WC_ELEMS) / 256, 256>>>(Wd, Wc);
    round_inputs_kernel<<<RND_F8 / 256, 256>>>((const float4*)down, (const float4*)skip);
    deconv_mma_kernel<<<dim3((N_DOWN + 127) / 128, K27), 256, D_SMEM>>>(d_iin, d_iout);
    relu_round_up_kernel<<<UP_F4 / 256, 256>>>();
    conv_mma_kernel<<<dim3(N_UP / 128, K27), 256, C_SMEM>>>(c_iin, c_iout, out);
    relu_kernel<<<OUT_F4 / 256, 256>>>((float4*)out);
}